// round 12
// baseline (speedup 1.0000x reference)
#include <cuda_runtime.h>

#define NUM_KPT 17
#define BATCH   64
#define HWC     6912           // 96*72
#define HW4     1728           // HWC/4
#define NBK     (BATCH * NUM_KPT)   // 1088
#define N_ELEM  7520256.0f     // 64*17*6912
#define NTHR    288            // 1728 / 288 = 6 iterations -> 3 unroll-2 macro-iterations
#define NWARP   (NTHR / 32)    // 9
#define NBLK    304            // persistent grid: 2 blocks/SM on 152 SMs

// scratch: per-(b,k) partials (every slot fully written each launch -> no init needed)
__device__ float g_A[NBK];
__device__ float g_Bv[NBK];
__device__ float g_P[NBK];
__device__ float g_Q[NBK];
__device__ unsigned int g_count = 0;   // arrival counter; reset by last block each launch

__device__ __forceinline__ float warp_sum(float v) {
    #pragma unroll
    for (int o = 16; o > 0; o >>= 1) v += __shfl_xor_sync(0xffffffffu, v, o);
    return v;
}

// release-ordered arrival: one instruction instead of MEMBAR.GPU + atomic
__device__ __forceinline__ unsigned int arrive_release(unsigned int* ctr) {
    unsigned int prev;
    asm volatile("atom.add.release.gpu.u32 %0, [%1], %2;"
                 : "=r"(prev) : "l"(ctr), "r"(1u) : "memory");
    return prev;
}

struct Ptrs {
    const float4 *O11, *O21, *T1, *O12x, *O12y, *O22x, *O22y, *T2x, *T2y;
};

// accumulate one float4-granule position into the 4 accumulators
__device__ __forceinline__ void accum(
    const Ptrs& p, int i,
    float& accA, float& accB, float& accP, float& accQ)
{
    float4 v11  = p.O11[i];
    float4 vt1  = p.T1[i];
    float4 v21  = p.O21[i];
    float4 v12x = p.O12x[i];
    float4 v12y = p.O12y[i];
    float4 v22x = p.O22x[i];
    float4 v22y = p.O22y[i];
    float4 vt2x = p.T2x[i];
    float4 vt2y = p.T2y[i];

    const float* p11  = &v11.x;
    const float* pt1  = &vt1.x;
    const float* p21  = &v21.x;
    const float* p12x = &v12x.x;
    const float* p12y = &v12y.x;
    const float* p22x = &v22x.x;
    const float* p22y = &v22y.x;
    const float* pt2x = &vt2x.x;
    const float* pt2y = &vt2y.x;

    #pragma unroll
    for (int l = 0; l < 4; l++) {
        float t  = pt1[l];
        float d1 = p11[l] - t;                 accA = fmaf(d1, d1, accA);
        float ex = fmaf(p12x[l], t, -pt2x[l]); accB = fmaf(ex, ex, accB);
        float ey = fmaf(p12y[l], t, -pt2y[l]); accB = fmaf(ey, ey, accB);
        float d2 = p21[l] - t;                 accP = fmaf(d2, d2, accP);
        float fx = p22x[l] - pt2x[l];
        float fy = p22y[l] - pt2y[l];
        float s  = fmaf(fx, fx, fy * fy);
        accQ = fmaf(s, t * t, accQ);
    }
}

// Persistent kernel: R8's proven per-channel mainloop (288 thr, unroll-2,
// 18 batched LDG.128, 2 blocks/SM), but each block strides through 3-4
// channels instead of exiting — removes wave transitions and per-CTA setup.
__global__ __launch_bounds__(NTHR, 2) void hrp_fused(
    const float* __restrict__ o11, const float* __restrict__ o12,
    const float* __restrict__ o21, const float* __restrict__ o22,
    const float* __restrict__ t1,  const float* __restrict__ t2,
    const float* __restrict__ weights, float* __restrict__ out)
{
    __shared__ float sAw[NWARP], sBw[NWARP], sPw[NWARP], sQw[NWARP];
    __shared__ bool isLast;

    const int wid = threadIdx.x >> 5, lid = threadIdx.x & 31;

    if (threadIdx.x == 0) isLast = false;
    __syncthreads();

    #pragma unroll 1
    for (int bk = blockIdx.x; bk < NBK; bk += NBLK) {
        const int b = bk / NUM_KPT;
        const int k = bk % NUM_KPT;

        const size_t base1 = (size_t)bk * HW4;                          // K-channel tensors
        const size_t basex = ((size_t)b * (2 * NUM_KPT) + k) * HW4;     // 2K tensors, x half
        const size_t basey = basex + (size_t)NUM_KPT * HW4;             // y half

        Ptrs p;
        p.O11  = (const float4*)o11 + base1;
        p.O21  = (const float4*)o21 + base1;
        p.T1   = (const float4*)t1  + base1;
        p.O12x = (const float4*)o12 + basex;
        p.O12y = (const float4*)o12 + basey;
        p.O22x = (const float4*)o22 + basex;
        p.O22y = (const float4*)o22 + basey;
        p.T2x  = (const float4*)t2  + basex;
        p.T2y  = (const float4*)t2  + basey;

        float accA = 0.f, accB = 0.f, accP = 0.f, accQ = 0.f;

        // 6 logical iterations = 3 macro-iterations of 2 (both payload sets batched)
        #pragma unroll 1
        for (int m = 0; m < 3; m++) {
            const int i0 = threadIdx.x + (2 * m) * NTHR;
            const int i1 = i0 + NTHR;
            accum(p, i0, accA, accB, accP, accQ);
            accum(p, i1, accA, accB, accP, accQ);
        }

        // block reduce (9 warps)
        accA = warp_sum(accA); accB = warp_sum(accB);
        accP = warp_sum(accP); accQ = warp_sum(accQ);
        if (lid == 0) { sAw[wid] = accA; sBw[wid] = accB; sPw[wid] = accP; sQw[wid] = accQ; }
        __syncthreads();

        if (threadIdx.x == 0) {
            float a = 0.f, bb = 0.f, pp = 0.f, q = 0.f;
            #pragma unroll
            for (int w = 0; w < NWARP; w++) { a += sAw[w]; bb += sBw[w]; pp += sPw[w]; q += sQw[w]; }
            g_A[bk] = a; g_Bv[bk] = bb; g_P[bk] = pp; g_Q[bk] = q;
            unsigned int prev = arrive_release(&g_count);   // release: partials visible first
            if (prev == NBK - 1u) isLast = true;
        }
        __syncthreads();   // protects sAw reuse next channel + isLast visibility
    }

    if (!isLast) return;

    // ---- final reduction: only the block that completed the last channel ----
    const int t = threadIdx.x;

    __shared__ float sP[NBK];   // staged per-(b,k) P
    __shared__ float sQ[NBK];   // staged per-(b,k) Q

    float a = 0.f, bb = 0.f;
    for (int i = t; i < NBK; i += NTHR) {
        sP[i] = g_P[i];
        sQ[i] = g_Q[i];
        a  += g_A[i];
        bb += g_Bv[i];
    }
    __syncthreads();

    // rank-based top-8 per batch (matches jax.lax.top_k: largest, lower index on ties)
    float l21 = 0.f, l22 = 0.f;
    if (t < BATCH) {
        const float* pv = &sP[t * NUM_KPT];
        #pragma unroll
        for (int kk = 0; kk < NUM_KPT; kk++) {
            float v = pv[kk];
            int r = 0;
            #pragma unroll
            for (int j = 0; j < NUM_KPT; j++) {
                float u = pv[j];
                r += (u > v) || (u == v && j < kk);
            }
            if (r < NUM_KPT / 2) {   // r < 8 -> selected
                l21 += v;
                l22 += sQ[t * NUM_KPT + kk];
            }
        }
    }

    // final block reduction: per-warp shuffles then 9 partials combined by thread 0
    a   = warp_sum(a);
    bb  = warp_sum(bb);
    l21 = warp_sum(l21);
    l22 = warp_sum(l22);
    __syncthreads();   // safe reuse of sAw.. after earlier phase
    if (lid == 0) { sAw[wid] = a; sBw[wid] = bb; sPw[wid] = l21; sQw[wid] = l22; }
    __syncthreads();

    if (t == 0) {
        float ra = 0.f, rb = 0.f, r21 = 0.f, r22 = 0.f;
        #pragma unroll
        for (int w = 0; w < NWARP; w++) { ra += sAw[w]; rb += sBw[w]; r21 += sPw[w]; r22 += sQw[w]; }
        float loss1_1 = ra / N_ELEM;
        float loss1_2 = rb / N_ELEM;
        float loss2_1 = r21 / (2.0f * BATCH) / (float)(BATCH * NUM_KPT);
        float loss2_2 = r22 / N_ELEM;
        float w0 = weights[0], w1 = weights[1];
        out[0] = (loss1_1 + loss2_1) * w0 + (loss1_2 + 5.0f * loss2_2) * w1;
        g_count = 0;                           // reset for next graph replay
    }
}

extern "C" void kernel_launch(void* const* d_in, const int* in_sizes, int n_in,
                              void* d_out, int out_size)
{
    const float* o11 = (const float*)d_in[0];
    const float* o12 = (const float*)d_in[1];
    const float* o21 = (const float*)d_in[2];
    const float* o22 = (const float*)d_in[3];
    const float* t1  = (const float*)d_in[4];
    const float* t2  = (const float*)d_in[5];
    const float* w   = (const float*)d_in[6];
    float* out = (float*)d_out;

    hrp_fused<<<NBLK, NTHR>>>(o11, o12, o21, o22, t1, t2, w, out);
}

// round 13
// speedup vs baseline: 1.0587x; 1.0587x over previous
#include <cuda_runtime.h>

#define NUM_KPT 17
#define BATCH   64
#define HWC     6912           // 96*72
#define HW4     1728           // HWC/4
#define NBK     (BATCH * NUM_KPT)   // 1088
#define N_ELEM  7520256.0f     // 64*17*6912
#define NTHR    288            // 1728 / 288 = 6 iterations -> 3 unroll-2 macro-iterations
#define NWARP   (NTHR / 32)    // 9

// scratch: per-(b,k) partials (every slot fully written each launch -> no init needed)
__device__ float g_A[NBK];
__device__ float g_Bv[NBK];
__device__ float g_P[NBK];
__device__ float g_Q[NBK];
__device__ unsigned int g_count = 0;   // arrival counter; reset by last block each launch

__device__ __forceinline__ float warp_sum(float v) {
    #pragma unroll
    for (int o = 16; o > 0; o >>= 1) v += __shfl_xor_sync(0xffffffffu, v, o);
    return v;
}

// release-ordered arrival: one instruction instead of MEMBAR.GPU + atomic
__device__ __forceinline__ unsigned int arrive_release(unsigned int* ctr) {
    unsigned int prev;
    asm volatile("atom.add.release.gpu.u32 %0, [%1], %2;"
                 : "=r"(prev) : "l"(ctr), "r"(1u) : "memory");
    return prev;
}

struct Ptrs {
    const float4 *O11, *O21, *T1, *O12x, *O12y, *O22x, *O22y, *T2x, *T2y;
};

// accumulate one float4-granule position into the 4 accumulators
__device__ __forceinline__ void accum(
    const Ptrs& p, int i,
    float& accA, float& accB, float& accP, float& accQ)
{
    float4 v11  = p.O11[i];
    float4 vt1  = p.T1[i];
    float4 v21  = p.O21[i];
    float4 v12x = p.O12x[i];
    float4 v12y = p.O12y[i];
    float4 v22x = p.O22x[i];
    float4 v22y = p.O22y[i];
    float4 vt2x = p.T2x[i];
    float4 vt2y = p.T2y[i];

    const float* p11  = &v11.x;
    const float* pt1  = &vt1.x;
    const float* p21  = &v21.x;
    const float* p12x = &v12x.x;
    const float* p12y = &v12y.x;
    const float* p22x = &v22x.x;
    const float* p22y = &v22y.x;
    const float* pt2x = &vt2x.x;
    const float* pt2y = &vt2y.x;

    #pragma unroll
    for (int l = 0; l < 4; l++) {
        float t  = pt1[l];
        float d1 = p11[l] - t;                 accA = fmaf(d1, d1, accA);
        float ex = fmaf(p12x[l], t, -pt2x[l]); accB = fmaf(ex, ex, accB);
        float ey = fmaf(p12y[l], t, -pt2y[l]); accB = fmaf(ey, ey, accB);
        float d2 = p21[l] - t;                 accP = fmaf(d2, d2, accP);
        float fx = p22x[l] - pt2x[l];
        float fy = p22y[l] - pt2y[l];
        float s  = fmaf(fx, fx, fy * fy);
        accQ = fmaf(s, t * t, accQ);
    }
}

// Measured-optimal config (session best: 46.85us ncu, 74.2% DRAM):
//   grid=1088 (1 channel/block, dynamic HW backfill), 288 thr, minblocks 2
//   (113-reg budget -> two full 9xfloat4 payload sets batched per macro-iter),
//   rolled 3x unroll-2 macro-loop (`#pragma unroll 1` boundary keeps the
//   18-LDG.128 front-batch intact).
// Bracketed alternatives all regressed: occ-8 cap (R3), 3-seg jobs (R6),
// unroll-3 (R9), full unroll (R10), persistent grid (R12).
__global__ __launch_bounds__(NTHR, 2) void hrp_fused(
    const float* __restrict__ o11, const float* __restrict__ o12,
    const float* __restrict__ o21, const float* __restrict__ o22,
    const float* __restrict__ t1,  const float* __restrict__ t2,
    const float* __restrict__ weights, float* __restrict__ out)
{
    const int bk = blockIdx.x;                 // 0..1087
    const int b  = bk / NUM_KPT;
    const int k  = bk % NUM_KPT;

    const size_t base1 = (size_t)bk * HW4;                          // K-channel tensors
    const size_t basex = ((size_t)b * (2 * NUM_KPT) + k) * HW4;     // 2K tensors, x half
    const size_t basey = basex + (size_t)NUM_KPT * HW4;             // y half

    Ptrs p;
    p.O11  = (const float4*)o11 + base1;
    p.O21  = (const float4*)o21 + base1;
    p.T1   = (const float4*)t1  + base1;
    p.O12x = (const float4*)o12 + basex;
    p.O12y = (const float4*)o12 + basey;
    p.O22x = (const float4*)o22 + basex;
    p.O22y = (const float4*)o22 + basey;
    p.T2x  = (const float4*)t2  + basex;
    p.T2y  = (const float4*)t2  + basey;

    float accA = 0.f, accB = 0.f, accP = 0.f, accQ = 0.f;

    // 6 logical iterations = 3 macro-iterations of 2 (both payload sets batched)
    #pragma unroll 1
    for (int m = 0; m < 3; m++) {
        const int i0 = threadIdx.x + (2 * m) * NTHR;
        const int i1 = i0 + NTHR;
        accum(p, i0, accA, accB, accP, accQ);
        accum(p, i1, accA, accB, accP, accQ);
    }

    // block reduce (9 warps)
    __shared__ float sAw[NWARP], sBw[NWARP], sPw[NWARP], sQw[NWARP];
    accA = warp_sum(accA); accB = warp_sum(accB);
    accP = warp_sum(accP); accQ = warp_sum(accQ);
    const int wid = threadIdx.x >> 5, lid = threadIdx.x & 31;
    if (lid == 0) { sAw[wid] = accA; sBw[wid] = accB; sPw[wid] = accP; sQw[wid] = accQ; }
    __syncthreads();

    __shared__ bool isLast;
    if (threadIdx.x == 0) {
        float a = 0.f, bb = 0.f, pp = 0.f, q = 0.f;
        #pragma unroll
        for (int w = 0; w < NWARP; w++) { a += sAw[w]; bb += sBw[w]; pp += sPw[w]; q += sQw[w]; }
        g_A[bk] = a; g_Bv[bk] = bb; g_P[bk] = pp; g_Q[bk] = q;
        unsigned int prev = arrive_release(&g_count);   // release: partials visible first
        isLast = (prev == NBK - 1u);
    }
    __syncthreads();
    if (!isLast) return;

    // ---- final reduction: only the last-arriving block runs this ----
    const int t = threadIdx.x;

    __shared__ float sP[NBK];   // staged per-(b,k) P
    __shared__ float sQ[NBK];   // staged per-(b,k) Q

    float a = 0.f, bb = 0.f;
    for (int i = t; i < NBK; i += NTHR) {
        sP[i] = g_P[i];
        sQ[i] = g_Q[i];
        a  += g_A[i];
        bb += g_Bv[i];
    }
    __syncthreads();

    // rank-based top-8 per batch (matches jax.lax.top_k: largest, lower index on ties)
    float l21 = 0.f, l22 = 0.f;
    if (t < BATCH) {
        const float* pv = &sP[t * NUM_KPT];
        #pragma unroll
        for (int kk = 0; kk < NUM_KPT; kk++) {
            float v = pv[kk];
            int r = 0;
            #pragma unroll
            for (int j = 0; j < NUM_KPT; j++) {
                float u = pv[j];
                r += (u > v) || (u == v && j < kk);
            }
            if (r < NUM_KPT / 2) {   // r < 8 -> selected
                l21 += v;
                l22 += sQ[t * NUM_KPT + kk];
            }
        }
    }

    // final block reduction: per-warp shuffles then 9 partials combined by thread 0
    a   = warp_sum(a);
    bb  = warp_sum(bb);
    l21 = warp_sum(l21);
    l22 = warp_sum(l22);
    __syncthreads();   // safe reuse of sAw.. after earlier phase
    if (lid == 0) { sAw[wid] = a; sBw[wid] = bb; sPw[wid] = l21; sQw[wid] = l22; }
    __syncthreads();

    if (t == 0) {
        float ra = 0.f, rb = 0.f, r21 = 0.f, r22 = 0.f;
        #pragma unroll
        for (int w = 0; w < NWARP; w++) { ra += sAw[w]; rb += sBw[w]; r21 += sPw[w]; r22 += sQw[w]; }
        float loss1_1 = ra / N_ELEM;
        float loss1_2 = rb / N_ELEM;
        float loss2_1 = r21 / (2.0f * BATCH) / (float)(BATCH * NUM_KPT);
        float loss2_2 = r22 / N_ELEM;
        float w0 = weights[0], w1 = weights[1];
        out[0] = (loss1_1 + loss2_1) * w0 + (loss1_2 + 5.0f * loss2_2) * w1;
        g_count = 0;                           // reset for next graph replay
    }
}

extern "C" void kernel_launch(void* const* d_in, const int* in_sizes, int n_in,
                              void* d_out, int out_size)
{
    const float* o11 = (const float*)d_in[0];
    const float* o12 = (const float*)d_in[1];
    const float* o21 = (const float*)d_in[2];
    const float* o22 = (const float*)d_in[3];
    const float* t1  = (const float*)d_in[4];
    const float* t2  = (const float*)d_in[5];
    const float* w   = (const float*)d_in[6];
    float* out = (float*)d_out;

    hrp_fused<<<NBK, NTHR>>>(o11, o12, o21, o22, t1, t2, w, out);
}

// round 14
// speedup vs baseline: 1.0914x; 1.0309x over previous
#include <cuda_runtime.h>

#define NUM_KPT 17
#define BATCH   64
#define HWC     6912           // 96*72
#define HW4     1728           // HWC/4
#define NBK     (BATCH * NUM_KPT)   // 1088
#define N_ELEM  7520256.0f     // 64*17*6912
#define NTHR    288            // 1728 / 288 = 6 iterations -> 3 unroll-2 macro-iterations
#define NWARP   (NTHR / 32)    // 9

// scratch: per-(b,k) partials (every slot fully written each launch -> no init needed)
__device__ float g_A[NBK];
__device__ float g_Bv[NBK];
__device__ float g_P[NBK];
__device__ float g_Q[NBK];
__device__ unsigned int g_count = 0;   // arrival counter; reset by last block each launch

__device__ __forceinline__ float warp_sum(float v) {
    #pragma unroll
    for (int o = 16; o > 0; o >>= 1) v += __shfl_xor_sync(0xffffffffu, v, o);
    return v;
}

// release-ordered arrival: one instruction instead of MEMBAR.GPU + atomic
__device__ __forceinline__ unsigned int arrive_release(unsigned int* ctr) {
    unsigned int prev;
    asm volatile("atom.add.release.gpu.u32 %0, [%1], %2;"
                 : "=r"(prev) : "l"(ctr), "r"(1u) : "memory");
    return prev;
}

struct Ptrs {
    const float4 *O11, *O21, *T1, *O12x, *O12y, *O22x, *O22y, *T2x, *T2y;
};

// accumulate one float4-granule position into the 4 accumulators
__device__ __forceinline__ void accum(
    const Ptrs& p, int i,
    float& accA, float& accB, float& accP, float& accQ)
{
    float4 v11  = p.O11[i];
    float4 vt1  = p.T1[i];
    float4 v21  = p.O21[i];
    float4 v12x = p.O12x[i];
    float4 v12y = p.O12y[i];
    float4 v22x = p.O22x[i];
    float4 v22y = p.O22y[i];
    float4 vt2x = p.T2x[i];
    float4 vt2y = p.T2y[i];

    const float* p11  = &v11.x;
    const float* pt1  = &vt1.x;
    const float* p21  = &v21.x;
    const float* p12x = &v12x.x;
    const float* p12y = &v12y.x;
    const float* p22x = &v22x.x;
    const float* p22y = &v22y.x;
    const float* pt2x = &vt2x.x;
    const float* pt2y = &vt2y.x;

    #pragma unroll
    for (int l = 0; l < 4; l++) {
        float t  = pt1[l];
        float d1 = p11[l] - t;                 accA = fmaf(d1, d1, accA);
        float ex = fmaf(p12x[l], t, -pt2x[l]); accB = fmaf(ex, ex, accB);
        float ey = fmaf(p12y[l], t, -pt2y[l]); accB = fmaf(ey, ey, accB);
        float d2 = p21[l] - t;                 accP = fmaf(d2, d2, accP);
        float fx = p22x[l] - pt2x[l];
        float fy = p22y[l] - pt2y[l];
        float s  = fmaf(fx, fx, fy * fy);
        accQ = fmaf(s, t * t, accQ);
    }
}

// CONVERGED CONFIG (session best 46.85us ncu / 47.58us timed, 74.2% DRAM):
//   grid=1088 (1 channel/block, dynamic HW backfill), 288 thr, minblocks 2
//   (113-reg budget -> two full 9xfloat4 payload sets batched per macro-iter),
//   rolled 3x unroll-2 macro-loop (`#pragma unroll 1` boundary keeps the
//   18-LDG.128 front-batch intact), fused last-block final reduction with
//   rank-based top-8 and release-ordered arrival.
// Every alternative bracketed and regressed: occ-8 cap (R3), 1/3-channel jobs
// (R6), unroll-3 (R9), full unroll (R10), persistent grid (R12), 2-kernel
// split (R1), __ldcs (R5 neutral). Run-to-run variance of this binary: +-1.2us.
__global__ __launch_bounds__(NTHR, 2) void hrp_fused(
    const float* __restrict__ o11, const float* __restrict__ o12,
    const float* __restrict__ o21, const float* __restrict__ o22,
    const float* __restrict__ t1,  const float* __restrict__ t2,
    const float* __restrict__ weights, float* __restrict__ out)
{
    const int bk = blockIdx.x;                 // 0..1087
    const int b  = bk / NUM_KPT;
    const int k  = bk % NUM_KPT;

    const size_t base1 = (size_t)bk * HW4;                          // K-channel tensors
    const size_t basex = ((size_t)b * (2 * NUM_KPT) + k) * HW4;     // 2K tensors, x half
    const size_t basey = basex + (size_t)NUM_KPT * HW4;             // y half

    Ptrs p;
    p.O11  = (const float4*)o11 + base1;
    p.O21  = (const float4*)o21 + base1;
    p.T1   = (const float4*)t1  + base1;
    p.O12x = (const float4*)o12 + basex;
    p.O12y = (const float4*)o12 + basey;
    p.O22x = (const float4*)o22 + basex;
    p.O22y = (const float4*)o22 + basey;
    p.T2x  = (const float4*)t2  + basex;
    p.T2y  = (const float4*)t2  + basey;

    float accA = 0.f, accB = 0.f, accP = 0.f, accQ = 0.f;

    // 6 logical iterations = 3 macro-iterations of 2 (both payload sets batched)
    #pragma unroll 1
    for (int m = 0; m < 3; m++) {
        const int i0 = threadIdx.x + (2 * m) * NTHR;
        const int i1 = i0 + NTHR;
        accum(p, i0, accA, accB, accP, accQ);
        accum(p, i1, accA, accB, accP, accQ);
    }

    // block reduce (9 warps)
    __shared__ float sAw[NWARP], sBw[NWARP], sPw[NWARP], sQw[NWARP];
    accA = warp_sum(accA); accB = warp_sum(accB);
    accP = warp_sum(accP); accQ = warp_sum(accQ);
    const int wid = threadIdx.x >> 5, lid = threadIdx.x & 31;
    if (lid == 0) { sAw[wid] = accA; sBw[wid] = accB; sPw[wid] = accP; sQw[wid] = accQ; }
    __syncthreads();

    __shared__ bool isLast;
    if (threadIdx.x == 0) {
        float a = 0.f, bb = 0.f, pp = 0.f, q = 0.f;
        #pragma unroll
        for (int w = 0; w < NWARP; w++) { a += sAw[w]; bb += sBw[w]; pp += sPw[w]; q += sQw[w]; }
        g_A[bk] = a; g_Bv[bk] = bb; g_P[bk] = pp; g_Q[bk] = q;
        unsigned int prev = arrive_release(&g_count);   // release: partials visible first
        isLast = (prev == NBK - 1u);
    }
    __syncthreads();
    if (!isLast) return;

    // ---- final reduction: only the last-arriving block runs this ----
    const int t = threadIdx.x;

    __shared__ float sP[NBK];   // staged per-(b,k) P
    __shared__ float sQ[NBK];   // staged per-(b,k) Q

    float a = 0.f, bb = 0.f;
    for (int i = t; i < NBK; i += NTHR) {
        sP[i] = g_P[i];
        sQ[i] = g_Q[i];
        a  += g_A[i];
        bb += g_Bv[i];
    }
    __syncthreads();

    // rank-based top-8 per batch (matches jax.lax.top_k: largest, lower index on ties)
    float l21 = 0.f, l22 = 0.f;
    if (t < BATCH) {
        const float* pv = &sP[t * NUM_KPT];
        #pragma unroll
        for (int kk = 0; kk < NUM_KPT; kk++) {
            float v = pv[kk];
            int r = 0;
            #pragma unroll
            for (int j = 0; j < NUM_KPT; j++) {
                float u = pv[j];
                r += (u > v) || (u == v && j < kk);
            }
            if (r < NUM_KPT / 2) {   // r < 8 -> selected
                l21 += v;
                l22 += sQ[t * NUM_KPT + kk];
            }
        }
    }

    // final block reduction: per-warp shuffles then 9 partials combined by thread 0
    a   = warp_sum(a);
    bb  = warp_sum(bb);
    l21 = warp_sum(l21);
    l22 = warp_sum(l22);
    __syncthreads();   // safe reuse of sAw.. after earlier phase
    if (lid == 0) { sAw[wid] = a; sBw[wid] = bb; sPw[wid] = l21; sQw[wid] = l22; }
    __syncthreads();

    if (t == 0) {
        float ra = 0.f, rb = 0.f, r21 = 0.f, r22 = 0.f;
        #pragma unroll
        for (int w = 0; w < NWARP; w++) { ra += sAw[w]; rb += sBw[w]; r21 += sPw[w]; r22 += sQw[w]; }
        float loss1_1 = ra / N_ELEM;
        float loss1_2 = rb / N_ELEM;
        float loss2_1 = r21 / (2.0f * BATCH) / (float)(BATCH * NUM_KPT);
        float loss2_2 = r22 / N_ELEM;
        float w0 = weights[0], w1 = weights[1];
        out[0] = (loss1_1 + loss2_1) * w0 + (loss1_2 + 5.0f * loss2_2) * w1;
        g_count = 0;                           // reset for next graph replay
    }
}

extern "C" void kernel_launch(void* const* d_in, const int* in_sizes, int n_in,
                              void* d_out, int out_size)
{
    const float* o11 = (const float*)d_in[0];
    const float* o12 = (const float*)d_in[1];
    const float* o21 = (const float*)d_in[2];
    const float* o22 = (const float*)d_in[3];
    const float* t1  = (const float*)d_in[4];
    const float* t2  = (const float*)d_in[5];
    const float* w   = (const float*)d_in[6];
    float* out = (float*)d_out;

    hrp_fused<<<NBK, NTHR>>>(o11, o12, o21, o22, t1, t2, w, out);
}

// round 15
// speedup vs baseline: 1.0921x; 1.0007x over previous
#include <cuda_runtime.h>

#define NUM_KPT 17
#define BATCH   64
#define HWC     6912           // 96*72
#define HW4     1728           // HWC/4
#define NBK     (BATCH * NUM_KPT)   // 1088
#define NBLK    (NBK / 2)           // 544 blocks, 2 adjacent channels each
#define N_ELEM  7520256.0f     // 64*17*6912
#define NTHR    288            // 1728 / 288 = 6 iterations -> 3 unroll-2 macro-iterations
#define NWARP   (NTHR / 32)    // 9

// scratch: per-(b,k) partials (every slot fully written each launch -> no init needed)
__device__ float g_A[NBK];
__device__ float g_Bv[NBK];
__device__ float g_P[NBK];
__device__ float g_Q[NBK];
__device__ unsigned int g_count = 0;   // arrival counter; reset by last block each launch

__device__ __forceinline__ float warp_sum(float v) {
    #pragma unroll
    for (int o = 16; o > 0; o >>= 1) v += __shfl_xor_sync(0xffffffffu, v, o);
    return v;
}

// release-ordered arrival: one instruction instead of MEMBAR.GPU + atomic
__device__ __forceinline__ unsigned int arrive_release(unsigned int* ctr) {
    unsigned int prev;
    asm volatile("atom.add.release.gpu.u32 %0, [%1], %2;"
                 : "=r"(prev) : "l"(ctr), "r"(1u) : "memory");
    return prev;
}

struct Ptrs {
    const float4 *O11, *O21, *T1, *O12x, *O12y, *O22x, *O22y, *T2x, *T2y;
};

__device__ __forceinline__ Ptrs make_ptrs(
    const float* o11, const float* o12, const float* o21, const float* o22,
    const float* t1, const float* t2, int bk)
{
    const int b = bk / NUM_KPT;
    const int k = bk % NUM_KPT;
    const size_t base1 = (size_t)bk * HW4;                          // K-channel tensors
    const size_t basex = ((size_t)b * (2 * NUM_KPT) + k) * HW4;     // 2K tensors, x half
    const size_t basey = basex + (size_t)NUM_KPT * HW4;             // y half
    Ptrs p;
    p.O11  = (const float4*)o11 + base1;
    p.O21  = (const float4*)o21 + base1;
    p.T1   = (const float4*)t1  + base1;
    p.O12x = (const float4*)o12 + basex;
    p.O12y = (const float4*)o12 + basey;
    p.O22x = (const float4*)o22 + basex;
    p.O22y = (const float4*)o22 + basey;
    p.T2x  = (const float4*)t2  + basex;
    p.T2y  = (const float4*)t2  + basey;
    return p;
}

// accumulate one float4-granule position into the 4 accumulators
__device__ __forceinline__ void accum(
    const Ptrs& p, int i,
    float& accA, float& accB, float& accP, float& accQ)
{
    float4 v11  = p.O11[i];
    float4 vt1  = p.T1[i];
    float4 v21  = p.O21[i];
    float4 v12x = p.O12x[i];
    float4 v12y = p.O12y[i];
    float4 v22x = p.O22x[i];
    float4 v22y = p.O22y[i];
    float4 vt2x = p.T2x[i];
    float4 vt2y = p.T2y[i];

    const float* p11  = &v11.x;
    const float* pt1  = &vt1.x;
    const float* p21  = &v21.x;
    const float* p12x = &v12x.x;
    const float* p12y = &v12y.x;
    const float* p22x = &v22x.x;
    const float* p22y = &v22y.x;
    const float* pt2x = &vt2x.x;
    const float* pt2y = &vt2y.x;

    #pragma unroll
    for (int l = 0; l < 4; l++) {
        float t  = pt1[l];
        float d1 = p11[l] - t;                 accA = fmaf(d1, d1, accA);
        float ex = fmaf(p12x[l], t, -pt2x[l]); accB = fmaf(ex, ex, accB);
        float ey = fmaf(p12y[l], t, -pt2y[l]); accB = fmaf(ey, ey, accB);
        float d2 = p21[l] - t;                 accP = fmaf(d2, d2, accP);
        float fx = p22x[l] - pt2x[l];
        float fy = p22y[l] - pt2y[l];
        float s  = fmaf(fx, fx, fy * fy);
        accQ = fmaf(s, t * t, accQ);
    }
}

// run the proven R8 mainloop for one channel (18 batched LDG.128 per macro-iter)
__device__ __forceinline__ void channel_loop(
    const Ptrs& p, float& accA, float& accB, float& accP, float& accQ)
{
    #pragma unroll 1
    for (int m = 0; m < 3; m++) {
        const int i0 = threadIdx.x + (2 * m) * NTHR;
        const int i1 = i0 + NTHR;
        accum(p, i0, accA, accB, accP, accQ);
        accum(p, i1, accA, accB, accP, accQ);
    }
}

// 2 adjacent channels per block: R8's mainloop twice back-to-back (no sync at
// the boundary), one epilogue (reduce + arrival) per block instead of per
// channel — halves the per-block dead phase while keeping dynamic backfill.
__global__ __launch_bounds__(NTHR, 2) void hrp_fused(
    const float* __restrict__ o11, const float* __restrict__ o12,
    const float* __restrict__ o21, const float* __restrict__ o22,
    const float* __restrict__ t1,  const float* __restrict__ t2,
    const float* __restrict__ weights, float* __restrict__ out)
{
    const int bk0 = blockIdx.x * 2;            // channels bk0, bk0+1
    const Ptrs p0 = make_ptrs(o11, o12, o21, o22, t1, t2, bk0);
    const Ptrs p1 = make_ptrs(o11, o12, o21, o22, t1, t2, bk0 + 1);

    float aA0 = 0.f, aB0 = 0.f, aP0 = 0.f, aQ0 = 0.f;
    float aA1 = 0.f, aB1 = 0.f, aP1 = 0.f, aQ1 = 0.f;

    channel_loop(p0, aA0, aB0, aP0, aQ0);      // channel A
    channel_loop(p1, aA1, aB1, aP1, aQ1);      // channel B (no sync between)

    // block reduce (9 warps), both channels
    __shared__ float sA0[NWARP], sB0[NWARP], sP0[NWARP], sQ0[NWARP];
    __shared__ float sA1[NWARP], sB1[NWARP], sP1[NWARP], sQ1[NWARP];
    aA0 = warp_sum(aA0); aB0 = warp_sum(aB0); aP0 = warp_sum(aP0); aQ0 = warp_sum(aQ0);
    aA1 = warp_sum(aA1); aB1 = warp_sum(aB1); aP1 = warp_sum(aP1); aQ1 = warp_sum(aQ1);
    const int wid = threadIdx.x >> 5, lid = threadIdx.x & 31;
    if (lid == 0) {
        sA0[wid] = aA0; sB0[wid] = aB0; sP0[wid] = aP0; sQ0[wid] = aQ0;
        sA1[wid] = aA1; sB1[wid] = aB1; sP1[wid] = aP1; sQ1[wid] = aQ1;
    }
    __syncthreads();

    __shared__ bool isLast;
    if (threadIdx.x == 0) {
        float a0 = 0.f, b0 = 0.f, q0 = 0.f, pp0 = 0.f;
        float a1 = 0.f, b1 = 0.f, q1 = 0.f, pp1 = 0.f;
        #pragma unroll
        for (int w = 0; w < NWARP; w++) {
            a0 += sA0[w]; b0 += sB0[w]; pp0 += sP0[w]; q0 += sQ0[w];
            a1 += sA1[w]; b1 += sB1[w]; pp1 += sP1[w]; q1 += sQ1[w];
        }
        g_A[bk0]     = a0; g_Bv[bk0]     = b0; g_P[bk0]     = pp0; g_Q[bk0]     = q0;
        g_A[bk0 + 1] = a1; g_Bv[bk0 + 1] = b1; g_P[bk0 + 1] = pp1; g_Q[bk0 + 1] = q1;
        unsigned int prev = arrive_release(&g_count);   // release: partials visible first
        isLast = (prev == NBLK - 1u);
    }
    __syncthreads();
    if (!isLast) return;

    // ---- final reduction: only the last-arriving block runs this ----
    const int t = threadIdx.x;

    __shared__ float sP[NBK];   // staged per-(b,k) P
    __shared__ float sQ[NBK];   // staged per-(b,k) Q

    float a = 0.f, bb = 0.f;
    for (int i = t; i < NBK; i += NTHR) {
        sP[i] = g_P[i];
        sQ[i] = g_Q[i];
        a  += g_A[i];
        bb += g_Bv[i];
    }
    __syncthreads();

    // rank-based top-8 per batch (matches jax.lax.top_k: largest, lower index on ties)
    float l21 = 0.f, l22 = 0.f;
    if (t < BATCH) {
        const float* pv = &sP[t * NUM_KPT];
        #pragma unroll
        for (int kk = 0; kk < NUM_KPT; kk++) {
            float v = pv[kk];
            int r = 0;
            #pragma unroll
            for (int j = 0; j < NUM_KPT; j++) {
                float u = pv[j];
                r += (u > v) || (u == v && j < kk);
            }
            if (r < NUM_KPT / 2) {   // r < 8 -> selected
                l21 += v;
                l22 += sQ[t * NUM_KPT + kk];
            }
        }
    }

    // final block reduction: per-warp shuffles then 9 partials combined by thread 0
    a   = warp_sum(a);
    bb  = warp_sum(bb);
    l21 = warp_sum(l21);
    l22 = warp_sum(l22);
    __syncthreads();   // safe reuse of sA0.. after earlier phase
    if (lid == 0) { sA0[wid] = a; sB0[wid] = bb; sP0[wid] = l21; sQ0[wid] = l22; }
    __syncthreads();

    if (t == 0) {
        float ra = 0.f, rb = 0.f, r21 = 0.f, r22 = 0.f;
        #pragma unroll
        for (int w = 0; w < NWARP; w++) { ra += sA0[w]; rb += sB0[w]; r21 += sP0[w]; r22 += sQ0[w]; }
        float loss1_1 = ra / N_ELEM;
        float loss1_2 = rb / N_ELEM;
        float loss2_1 = r21 / (2.0f * BATCH) / (float)(BATCH * NUM_KPT);
        float loss2_2 = r22 / N_ELEM;
        float w0 = weights[0], w1 = weights[1];
        out[0] = (loss1_1 + loss2_1) * w0 + (loss1_2 + 5.0f * loss2_2) * w1;
        g_count = 0;                           // reset for next graph replay
    }
}

extern "C" void kernel_launch(void* const* d_in, const int* in_sizes, int n_in,
                              void* d_out, int out_size)
{
    const float* o11 = (const float*)d_in[0];
    const float* o12 = (const float*)d_in[1];
    const float* o21 = (const float*)d_in[2];
    const float* o22 = (const float*)d_in[3];
    const float* t1  = (const float*)d_in[4];
    const float* t2  = (const float*)d_in[5];
    const float* w   = (const float*)d_in[6];
    float* out = (float*)d_out;

    hrp_fused<<<NBLK, NTHR>>>(o11, o12, o21, o22, t1, t2, w, out);
}